// round 5
// baseline (speedup 1.0000x reference)
#include <cuda_runtime.h>
#include <cuda_bf16.h>

#define FEAT 128
#define NUM_GRAPHS 10000

// ---------------------------------------------------------------------------
// Zero the output (harness poisons d_out with 0xAA).
// ---------------------------------------------------------------------------
__global__ void zero_kernel(float4* __restrict__ out, int n4) {
    int i = blockIdx.x * blockDim.x + threadIdx.x;
    if (i < n4) out[i] = make_float4(0.f, 0.f, 0.f, 0.f);
}

// ---------------------------------------------------------------------------
// Sorted segment-sum.
// Each warp owns a contiguous chunk of rows. Lane l accumulates features
// [4l, 4l+4) in a float4 register while the segment id is unchanged; flush
// with atomicAdd (RED, no return) only at segment boundaries / chunk edges.
// Software-pipelined one row ahead so the next LDG.128 is in flight before
// the compare/branch.
// batch is int32 (JAX x64-disabled downcasts the reference's int64).
// ---------------------------------------------------------------------------
__global__ __launch_bounds__(256, 8) void segsum_kernel(
    const float4* __restrict__ hv,          // h_t viewed as [n_rows][32] float4
    const int* __restrict__ batch,          // sorted segment ids, int32
    float* __restrict__ out,                // [NUM_GRAPHS][FEAT]
    int n_rows)
{
    const int lane        = threadIdx.x & 31;
    const int gwarp       = (blockIdx.x * blockDim.x + threadIdx.x) >> 5;
    const int total_warps = (gridDim.x * blockDim.x) >> 5;

    // Contiguous, balanced row chunk for this warp.
    const int start = (int)(((long long)n_rows * gwarp) / total_warps);
    const int end   = (int)(((long long)n_rows * (gwarp + 1)) / total_warps);
    if (start >= end) return;

    float4 acc = make_float4(0.f, 0.f, 0.f, 0.f);
    int    cur = batch[start];

    // Prime the pipeline: row `start` loaded.
    int    r = start;
    int    b = cur;
    float4 v = hv[(long long)r * (FEAT / 4) + lane];

    for (;;) {
        // Prefetch next row before touching this one (keeps an LDG.128 +
        // uniform LDG in flight across the branch below).
        const int  rn       = r + 1;
        const bool has_next = (rn < end);
        int    bn = 0;
        float4 vn = make_float4(0.f, 0.f, 0.f, 0.f);
        if (has_next) {
            bn = batch[rn];
            vn = hv[(long long)rn * (FEAT / 4) + lane];
        }

        if (b != cur) {
            // Segment boundary: flush accumulator (rare — avg ~100 rows/seg).
            float* o = out + (long long)cur * FEAT + lane * 4;
            atomicAdd(o + 0, acc.x);
            atomicAdd(o + 1, acc.y);
            atomicAdd(o + 2, acc.z);
            atomicAdd(o + 3, acc.w);
            cur = b;
            acc = v;
        } else {
            acc.x += v.x; acc.y += v.y; acc.z += v.z; acc.w += v.w;
        }

        if (!has_next) break;
        r = rn; b = bn; v = vn;
    }

    // Final flush for this warp's chunk (chunk may end mid-segment, and the
    // neighboring warp shares the segment -> must be atomic).
    float* o = out + (long long)cur * FEAT + lane * 4;
    atomicAdd(o + 0, acc.x);
    atomicAdd(o + 1, acc.y);
    atomicAdd(o + 2, acc.z);
    atomicAdd(o + 3, acc.w);
}

// ---------------------------------------------------------------------------
// Harness entry point.
//   d_in[0] : h_t   float32 [N_NODES * FEAT]
//   d_in[1] : batch int32   [N_NODES]   (JAX downcasts int64 -> int32)
//   d_out   : float32 [NUM_GRAPHS * FEAT]
// ---------------------------------------------------------------------------
extern "C" void kernel_launch(void* const* d_in, const int* in_sizes, int n_in,
                              void* d_out, int out_size) {
    const float4* hv    = (const float4*)d_in[0];
    const int*    batch = (const int*)d_in[1];
    float*        out   = (float*)d_out;
    const int n_rows = in_sizes[1];          // number of nodes

    // 1) Zero the (poisoned) output.
    const int n4 = out_size / 4;             // float4 count
    zero_kernel<<<(n4 + 255) / 256, 256>>>((float4*)d_out, n4);

    // 2) Segment sum. 2048 blocks x 8 warps = 16384 warps (~61 rows each),
    //    ~1.8 waves at 64 warps/SM on 148+ SMs.
    segsum_kernel<<<2048, 256>>>(hv, batch, out, n_rows);
}